// round 12
// baseline (speedup 1.0000x reference)
#include <cuda_runtime.h>
#include <cuda_fp16.h>

// ---------------------------------------------------------------------------
// Problem constants
// ---------------------------------------------------------------------------
#define Bn   4
#define Ln   2048
#define Dn   1024
#define Hn   16
#define Kd   64
#define LDf  (Ln * Dn)       // 2097152 floats per batch
#define HSTRd (Ln * Kd)      // 131072: contiguous per-head [2048,64] block

// ---------------------------------------------------------------------------
// Scratch (static __device__ — allocation-free rule)
// ---------------------------------------------------------------------------
__device__ __half g_xh[Bn * LDf],     g_xl[Bn * LDf];      // x split
__device__ __half g_wqh[Dn * 3 * Dn];                      // wqkv fp16
__device__ __half g_woh[Dn * Dn];                          // wo fp16
__device__ __half g_qh[Bn * LDf];                          // q fp16
__device__ __half g_kh[Bn * LDf];                          // k fp16
__device__ __half g_vh[Bn * LDf];                          // v fp16
__device__ __half g_ah[Bn * LDf],     g_al[Bn * LDf];      // attended split
__device__ __half g_p[(size_t)Bn * Hn * Ln * Ln];          // 512MB: exp(S/8) fp16
__device__ float  g_zi[(size_t)Bn * Ln * Ln];              // 64MB: 1/z

// ---------------------------------------------------------------------------
// PTX helpers
// ---------------------------------------------------------------------------
__device__ __forceinline__ unsigned sptr(const void* p) {
    return (unsigned)__cvta_generic_to_shared(p);
}
__device__ __forceinline__ void ldsm_x4(unsigned &r0, unsigned &r1, unsigned &r2, unsigned &r3, unsigned a) {
    asm volatile("ldmatrix.sync.aligned.m8n8.x4.shared.b16 {%0,%1,%2,%3},[%4];\n"
                 : "=r"(r0), "=r"(r1), "=r"(r2), "=r"(r3) : "r"(a));
}
__device__ __forceinline__ void ldsm_x4t(unsigned &r0, unsigned &r1, unsigned &r2, unsigned &r3, unsigned a) {
    asm volatile("ldmatrix.sync.aligned.m8n8.x4.trans.shared.b16 {%0,%1,%2,%3},[%4];\n"
                 : "=r"(r0), "=r"(r1), "=r"(r2), "=r"(r3) : "r"(a));
}
__device__ __forceinline__ void ldsm_x2(unsigned &r0, unsigned &r1, unsigned a) {
    asm volatile("ldmatrix.sync.aligned.m8n8.x2.shared.b16 {%0,%1},[%2];\n"
                 : "=r"(r0), "=r"(r1) : "r"(a));
}
__device__ __forceinline__ void mma16816(float* c, unsigned a0, unsigned a1, unsigned a2, unsigned a3,
                                         unsigned b0, unsigned b1) {
    asm volatile("mma.sync.aligned.m16n8k16.row.col.f32.f16.f16.f32 "
                 "{%0,%1,%2,%3},{%4,%5,%6,%7},{%8,%9},{%0,%1,%2,%3};\n"
                 : "+f"(c[0]), "+f"(c[1]), "+f"(c[2]), "+f"(c[3])
                 : "r"(a0), "r"(a1), "r"(a2), "r"(a3), "r"(b0), "r"(b1));
}
__device__ __forceinline__ void cp16(unsigned d, const void* s) {
    asm volatile("cp.async.cg.shared.global [%0],[%1],16;\n" :: "r"(d), "l"(s) : "memory");
}
__device__ __forceinline__ void cp_commit() {
    asm volatile("cp.async.commit_group;\n" ::: "memory");
}
__device__ __forceinline__ void cp_wait1() {
    asm volatile("cp.async.wait_group 1;\n" ::: "memory");
}

// ---------------------------------------------------------------------------
// FMA-pipe exp: exp(s/8) via exp2 with magic rounding + deg-5 poly.
// ---------------------------------------------------------------------------
__device__ __forceinline__ float fast_exp8(float s) {
    const float MAGIC = 12582912.f;               // 1.5 * 2^23
    float y = __fmul_rn(s, 0.18033688011112042f); // 0.125 * log2(e)
    float t = __fadd_rn(y, MAGIC);
    float f = __fsub_rn(y, __fsub_rn(t, MAGIC));  // frac in [-0.5, 0.5]
    int   e = (__float_as_int(t) - 0x4B400000) << 23;
    float p =              1.3333558e-3f;
    p = fmaf(p, f, 9.6181291e-3f);
    p = fmaf(p, f, 5.5504109e-2f);
    p = fmaf(p, f, 2.4022651e-1f);
    p = fmaf(p, f, 6.9314718e-1f);
    p = fmaf(p, f, 1.0f);
    return __int_as_float(__float_as_int(p) + e);
}

__device__ __forceinline__ void split_store2(__half* Hh, __half* Hl, size_t off, float c0, float c1) {
    __half h0 = __float2half(c0), h1 = __float2half(c1);
    float  r0 = c0 - __half2float(h0), r1 = c1 - __half2float(h1);
    *(__half2*)&Hh[off] = __halves2half2(h0, h1);
    *(__half2*)&Hl[off] = __floats2half2_rn(r0, r1);
}

// ---------------------------------------------------------------------------
// Split fp32 -> fp16.
//   which 0: x    -> g_xh + g_xl  (hi/lo)
//   which 1: wqkv -> g_wqh        (hi only)
//   which 2: wo   -> g_woh        (hi only)
// ---------------------------------------------------------------------------
__global__ void split_kernel(const float* __restrict__ src, int which, int n)
{
    for (int i = blockIdx.x * blockDim.x + threadIdx.x; i < n; i += gridDim.x * blockDim.x) {
        float v = src[i];
        __half h = __float2half(v);
        if (which == 0) {
            g_xh[i] = h;
            g_xl[i] = __float2half(v - __half2float(h));
        } else if (which == 1) {
            g_wqh[i] = h;
        } else {
            g_woh[i] = h;
        }
    }
}

// ---------------------------------------------------------------------------
// Split-precision GEMM: logical K' = 2*1024, segments [Ah|Al] x [Bh|Bh]
// (A exact via hi/lo pair, weights fp16-quantized).
// CTA 128x256, 256 thr = 8 warps (2x4), warp tile 64x64, BK=32,
// 3-stage cp.async pipeline. High-ILP / low-occupancy (CUTLASS-style).
// mode 0: A = x split, B = wqkv; epilogue -> q/k/v fp16.
// mode 1: A = att split, B = wo; epilogue -> fp32 outp.
// ---------------------------------------------------------------------------
#define GS_STAGE (128 * 40 + 32 * 264)   // halfs per stage = 13568

__global__ __launch_bounds__(256, 1) void gemm_split(int mode, float* __restrict__ outp)
{
    extern __shared__ __align__(16) __half gsm[];

    const int t = threadIdx.x, lane = t & 31, wid = t >> 5;
    const int wm = wid >> 2, wn = wid & 3;           // 2 x 4 warps
    const int m0 = blockIdx.y * 128;
    const int n0 = blockIdx.x * 256;

    const __half* __restrict__ Ahp = mode ? g_ah  : g_xh;
    const __half* __restrict__ Alp = mode ? g_al  : g_xl;
    const __half* __restrict__ Bhp = mode ? g_woh : g_wqh;
    const int Nw = mode ? 1024 : 3072;
    const int NIT = 64;                              // 2 segments * 32 k-steps

    const int arow = t >> 1, acol = (t & 1) * 16;    // A: 128x32 halfs, 2 cp16/thr
    const int brow = t >> 3, bcol = (t & 7) * 32;    // B: 32x256 halfs, 4 cp16/thr
    const size_t aoff = (size_t)(m0 + arow) * 1024 + acol;
    const size_t boff = (size_t)brow * Nw + n0 + bcol;

    auto issue = [&](int it) {
        const int sg = it >> 5;
        const int k0 = (it & 31) * 32;
        const __half* Ap = sg ? Alp : Ahp;
        __half* S  = gsm + (it % 3) * GS_STAGE;
        unsigned da = sptr(S + arow * 40 + acol);
        unsigned db = sptr(S + 128 * 40 + brow * 264 + bcol);
        const __half* ga = Ap + aoff + k0;
        const __half* gb = Bhp + boff + (size_t)k0 * Nw;
        cp16(da,      ga);
        cp16(da + 16, ga + 8);
        cp16(db,      gb);
        cp16(db + 16, gb + 8);
        cp16(db + 32, gb + 16);
        cp16(db + 48, gb + 24);
        cp_commit();
    };

    float acc[4][8][4];
#pragma unroll
    for (int i = 0; i < 4; i++)
#pragma unroll
        for (int j = 0; j < 8; j++)
#pragma unroll
            for (int c = 0; c < 4; c++) acc[i][j][c] = 0.f;

    issue(0);
    issue(1);

    for (int it = 0; it < NIT; it++) {
        cp_wait1();
        __syncthreads();
        if (it + 2 < NIT) issue(it + 2);

        __half (*As)[40]  = (__half(*)[40]) (gsm + (it % 3) * GS_STAGE);
        __half (*Bs)[264] = (__half(*)[264])(gsm + (it % 3) * GS_STAGE + 128 * 40);

#pragma unroll
        for (int kk = 0; kk < 2; kk++) {
            const int kb = kk * 16;
            unsigned a[4][4];
#pragma unroll
            for (int mi = 0; mi < 4; mi++)
                ldsm_x4(a[mi][0], a[mi][1], a[mi][2], a[mi][3],
                        sptr(&As[wm * 64 + mi * 16 + (lane & 15)][kb + (lane >> 4) * 8]));
            unsigned bf[8][2];
#pragma unroll
            for (int hb = 0; hb < 4; hb++) {
                unsigned r0, r1, r2, r3;
                ldsm_x4t(r0, r1, r2, r3,
                         sptr(&Bs[kb + (lane & 15)][wn * 64 + hb * 16 + (lane >> 4) * 8]));
                bf[hb * 2][0] = r0;  bf[hb * 2][1] = r1;
                bf[hb * 2 + 1][0] = r2;  bf[hb * 2 + 1][1] = r3;
            }
#pragma unroll
            for (int mi = 0; mi < 4; mi++)
#pragma unroll
                for (int ni = 0; ni < 8; ni++)
                    mma16816(acc[mi][ni], a[mi][0], a[mi][1], a[mi][2], a[mi][3],
                             bf[ni][0], bf[ni][1]);
        }
    }

    // Epilogue
#pragma unroll
    for (int mi = 0; mi < 4; mi++) {
#pragma unroll
        for (int ni = 0; ni < 8; ni++) {
            const int gm = m0 + wm * 64 + mi * 16 + (lane >> 2);
            const int gn = n0 + wn * 64 + ni * 8 + (lane & 3) * 2;
            if (mode == 1) {
                *(float2*)&outp[(size_t)gm * 1024 + gn]       = make_float2(acc[mi][ni][0], acc[mi][ni][1]);
                *(float2*)&outp[(size_t)(gm + 8) * 1024 + gn] = make_float2(acc[mi][ni][2], acc[mi][ni][3]);
            } else {
                const int part = gn >> 10, lc = gn & 1023;
                __half* Hh = (part == 0) ? g_qh : (part == 1) ? g_kh : g_vh;
                *(__half2*)&Hh[(size_t)gm * 1024 + lc] =
                    __floats2half2_rn(acc[mi][ni][0], acc[mi][ni][1]);
                *(__half2*)&Hh[(size_t)(gm + 8) * 1024 + lc] =
                    __floats2half2_rn(acc[mi][ni][2], acc[mi][ni][3]);
            }
        }
    }
}

// ---------------------------------------------------------------------------
// Pass A: per (b, 128-l, 64-m) tile, loop h: S = Qh·Kh (fp16 single pass),
// P = exp(S/8) -> g_p (fp16), z += P; then zinv -> g_zi.
// Dynamic smem: Qh[128][72] + Kh[64][72] = 27648 B.
// ---------------------------------------------------------------------------
__global__ __launch_bounds__(256, 2) void zsum_kernel()
{
    extern __shared__ __half zsm[];
    __half (*Qh)[72] = (__half(*)[72])zsm;
    __half (*Kh)[72] = (__half(*)[72])(zsm + 128 * 72);

    const int t = threadIdx.x, lane = t & 31, wid = t >> 5;
    const int wm = wid >> 1, wn = wid & 1;          // 4 x 2, warp tile 32(l) x 32(m)
    const int m0 = blockIdx.x * 64;
    const int l0 = blockIdx.y * 128;
    const int b  = blockIdx.z;

    float zacc[2][4][4];
#pragma unroll
    for (int i = 0; i < 2; i++)
#pragma unroll
        for (int j = 0; j < 4; j++)
#pragma unroll
            for (int c = 0; c < 4; c++) zacc[i][j][c] = 0.f;

    const int qr = t >> 1, qc = (t & 1) * 32;       // Q tile: 4 uint4/thr
    const int kr = t >> 2, kc = (t & 3) * 16;       // K tile: 2 uint4/thr

    for (int h = 0; h < Hn; h++) {
        const size_t qbase = (size_t)b * LDf + (size_t)h * HSTRd + (size_t)l0 * Kd;
        const size_t kbase = (size_t)b * LDf + (size_t)h * HSTRd + (size_t)m0 * Kd;
        __syncthreads();
#pragma unroll
        for (int i = 0; i < 4; i++) {
            *(uint4*)&Qh[qr][qc + i * 8] = *(const uint4*)(g_qh + qbase + (size_t)qr * Kd + qc + i * 8);
        }
#pragma unroll
        for (int i = 0; i < 2; i++) {
            *(uint4*)&Kh[kr][kc + i * 8] = *(const uint4*)(g_kh + kbase + (size_t)kr * Kd + kc + i * 8);
        }
        __syncthreads();

        float sacc[2][4][4];
#pragma unroll
        for (int i = 0; i < 2; i++)
#pragma unroll
            for (int j = 0; j < 4; j++)
#pragma unroll
                for (int c = 0; c < 4; c++) sacc[i][j][c] = 0.f;

#pragma unroll
        for (int kk = 0; kk < 4; kk++) {
            const int kb = kk * 16;
            unsigned a[2][4];
#pragma unroll
            for (int mi = 0; mi < 2; mi++)
                ldsm_x4(a[mi][0], a[mi][1], a[mi][2], a[mi][3],
                        sptr(&Qh[wm * 32 + mi * 16 + (lane & 15)][kb + (lane >> 4) * 8]));
            unsigned bf[4][2];
#pragma unroll
            for (int ni = 0; ni < 4; ni++)
                ldsm_x2(bf[ni][0], bf[ni][1],
                        sptr(&Kh[wn * 32 + ni * 8 + (lane & 7)][kb + ((lane >> 3) & 1) * 8]));
#pragma unroll
            for (int mi = 0; mi < 2; mi++)
#pragma unroll
                for (int ni = 0; ni < 4; ni++)
                    mma16816(sacc[mi][ni], a[mi][0], a[mi][1], a[mi][2], a[mi][3],
                             bf[ni][0], bf[ni][1]);
        }

        // exp (FMA-pipe poly), accumulate z, write P
        const size_t pbase = (size_t)(b * Hn + h) * Ln * Ln;
#pragma unroll
        for (int mi = 0; mi < 2; mi++) {
#pragma unroll
            for (int ni = 0; ni < 4; ni++) {
                const int gl = l0 + wm * 32 + mi * 16 + (lane >> 2);
                const int gm = m0 + wn * 32 + ni * 8 + (lane & 3) * 2;
                float p0 = fast_exp8(sacc[mi][ni][0]);
                float p1 = fast_exp8(sacc[mi][ni][1]);
                float p2 = fast_exp8(sacc[mi][ni][2]);
                float p3 = fast_exp8(sacc[mi][ni][3]);
                zacc[mi][ni][0] += p0; zacc[mi][ni][1] += p1;
                zacc[mi][ni][2] += p2; zacc[mi][ni][3] += p3;
                *(__half2*)&g_p[pbase + (size_t)gl * Ln + gm]       = __floats2half2_rn(p0, p1);
                *(__half2*)&g_p[pbase + (size_t)(gl + 8) * Ln + gm] = __floats2half2_rn(p2, p3);
            }
        }
    }

    // zinv
#pragma unroll
    for (int mi = 0; mi < 2; mi++) {
#pragma unroll
        for (int ni = 0; ni < 4; ni++) {
            const int gl = l0 + wm * 32 + mi * 16 + (lane >> 2);
            const int gm = m0 + wn * 32 + ni * 8 + (lane & 3) * 2;
            *(float2*)&g_zi[((size_t)b * Ln + gl) * Ln + gm] =
                make_float2(__fdividef(1.f, zacc[mi][ni][0]), __fdividef(1.f, zacc[mi][ni][1]));
            *(float2*)&g_zi[((size_t)b * Ln + gl + 8) * Ln + gm] =
                make_float2(__fdividef(1.f, zacc[mi][ni][2]), __fdividef(1.f, zacc[mi][ni][3]));
        }
    }
}

// ---------------------------------------------------------------------------
// Pass B: O[128 l, 64 kd] = sum_m (P * zinv) @ Vh  per (b, h, l-tile).
// Static smem: Ps[128][72] + Vhs[64][72] = 27648 B.
// ---------------------------------------------------------------------------
__global__ __launch_bounds__(256, 2) void apv_kernel()
{
    __shared__ __half Ps[128][72];
    __shared__ __half Vhs[64][72];

    const int t = threadIdx.x, lane = t & 31, wid = t >> 5;
    const int wm = wid >> 1, wn = wid & 1;          // 4 x 2, warp tile 32(l) x 32(kd)
    const int l0 = blockIdx.x * 128;
    const int h  = blockIdx.y;
    const int b  = blockIdx.z;

    float acc[2][4][4];
#pragma unroll
    for (int i = 0; i < 2; i++)
#pragma unroll
        for (int j = 0; j < 4; j++)
#pragma unroll
            for (int c = 0; c < 4; c++) acc[i][j][c] = 0.f;

    const size_t vbase = (size_t)b * LDf + (size_t)h * HSTRd;
    const size_t pbase = (size_t)(b * Hn + h) * Ln * Ln + (size_t)l0 * Ln;
    const size_t zbase = ((size_t)b * Ln + l0) * Ln;

    const int pr = t >> 1, pc = (t & 1) * 32;       // P/z rows
    const int vr = t >> 2, vc = (t & 3) * 16;       // V rows

    for (int m0 = 0; m0 < Ln; m0 += 64) {
        __syncthreads();
#pragma unroll
        for (int i = 0; i < 4; i++) {
            const size_t po = (size_t)pr * Ln + m0 + pc + i * 8;
            uint4 pv = *(const uint4*)(g_p + pbase + po);
            float4 za = *(const float4*)(g_zi + zbase + po);
            float4 zb = *(const float4*)(g_zi + zbase + po + 4);
            __half2* ph = (__half2*)&pv;
            uint4 ov;
            __half2* po2 = (__half2*)&ov;
            float2 f;
            f = __half22float2(ph[0]); po2[0] = __floats2half2_rn(f.x * za.x, f.y * za.y);
            f = __half22float2(ph[1]); po2[1] = __floats2half2_rn(f.x * za.z, f.y * za.w);
            f = __half22float2(ph[2]); po2[2] = __floats2half2_rn(f.x * zb.x, f.y * zb.y);
            f = __half22float2(ph[3]); po2[3] = __floats2half2_rn(f.x * zb.z, f.y * zb.w);
            *(uint4*)&Ps[pr][pc + i * 8] = ov;
        }
#pragma unroll
        for (int i = 0; i < 2; i++) {
            *(uint4*)&Vhs[vr][vc + i * 8] = *(const uint4*)(g_vh + vbase + (size_t)(m0 + vr) * Kd + vc + i * 8);
        }
        __syncthreads();

#pragma unroll
        for (int kk = 0; kk < 4; kk++) {
            const int kb = kk * 16;
            unsigned a[2][4];
#pragma unroll
            for (int mi = 0; mi < 2; mi++)
                ldsm_x4(a[mi][0], a[mi][1], a[mi][2], a[mi][3],
                        sptr(&Ps[wm * 32 + mi * 16 + (lane & 15)][kb + (lane >> 4) * 8]));
            unsigned bh[4][2];
#pragma unroll
            for (int hb = 0; hb < 2; hb++) {
                unsigned r0, r1, r2, r3;
                ldsm_x4t(r0, r1, r2, r3,
                         sptr(&Vhs[kb + (lane & 15)][wn * 32 + hb * 16 + (lane >> 4) * 8]));
                bh[hb * 2][0] = r0; bh[hb * 2][1] = r1; bh[hb * 2 + 1][0] = r2; bh[hb * 2 + 1][1] = r3;
            }
#pragma unroll
            for (int mi = 0; mi < 2; mi++)
#pragma unroll
                for (int ni = 0; ni < 4; ni++)
                    mma16816(acc[mi][ni], a[mi][0], a[mi][1], a[mi][2], a[mi][3], bh[ni][0], bh[ni][1]);
        }
    }

    // Epilogue: split-write attended in concatted layout [b, l, h*64 + kd]
#pragma unroll
    for (int mi = 0; mi < 2; mi++) {
#pragma unroll
        for (int ni = 0; ni < 4; ni++) {
            const int gl = l0 + wm * 32 + mi * 16 + (lane >> 2);
            const int gc = h * Kd + wn * 32 + ni * 8 + (lane & 3) * 2;
            split_store2(g_ah, g_al, ((size_t)b * Ln + gl) * 1024 + gc,
                         acc[mi][ni][0], acc[mi][ni][1]);
            split_store2(g_ah, g_al, ((size_t)b * Ln + gl + 8) * 1024 + gc,
                         acc[mi][ni][2], acc[mi][ni][3]);
        }
    }
}

// ---------------------------------------------------------------------------
// Launch
// ---------------------------------------------------------------------------
extern "C" void kernel_launch(void* const* d_in, const int* in_sizes, int n_in,
                              void* d_out, int out_size)
{
    const float* x    = (const float*)d_in[0];
    const float* wqkv = (const float*)d_in[1];
    const float* wo   = (const float*)d_in[2];
    float* out = (float*)d_out;

    cudaFuncSetAttribute(gemm_split, cudaFuncAttributeMaxDynamicSharedMemorySize, GS_STAGE * 3 * 2);
    cudaFuncSetAttribute(zsum_kernel, cudaFuncAttributeMaxDynamicSharedMemorySize, 27648);

    // 0) fp32 -> fp16 splits
    split_kernel<<<4096, 256>>>(x,    0, Bn * LDf);
    split_kernel<<<2048, 256>>>(wqkv, 1, Dn * 3 * Dn);
    split_kernel<<<1024, 256>>>(wo,   2, Dn * Dn);

    // 1) QKV projection (2-pass split GEMM, 128x256 CTA) -> q/k/v fp16
    gemm_split<<<dim3(12, 64), 256, GS_STAGE * 3 * 2>>>(0, nullptr);

    // 2) Pass A: P = exp(QK^T/8) -> g_p,  zinv over head axis -> g_zi
    zsum_kernel<<<dim3(32, 16, 4), 256, 27648>>>();

    // 3) Pass B: O = (P * zinv) @ Vh -> g_att hi+lo (concatted layout)
    apv_kernel<<<dim3(16, 16, 4), 256>>>();

    // 4) Output projection (2-pass split GEMM: attended exact, wo fp16) -> d_out
    gemm_split<<<dim3(4, 64), 256, GS_STAGE * 3 * 2>>>(1, out);
}

// round 13
// speedup vs baseline: 1.0819x; 1.0819x over previous
#include <cuda_runtime.h>
#include <cuda_fp16.h>

// ---------------------------------------------------------------------------
// Problem constants
// ---------------------------------------------------------------------------
#define Bn   4
#define Ln   2048
#define Dn   1024
#define Hn   16
#define Kd   64
#define LDf  (Ln * Dn)       // 2097152 floats per batch
#define HSTRd (Ln * Kd)      // 131072: contiguous per-head [2048,64] block

// ---------------------------------------------------------------------------
// Scratch (static __device__ — allocation-free rule)
// ---------------------------------------------------------------------------
__device__ __half g_xh[Bn * LDf],     g_xl[Bn * LDf];      // x split
__device__ __half g_wqh[Dn * 3 * Dn];                      // wqkv fp16
__device__ __half g_woh[Dn * Dn];                          // wo fp16
__device__ __half g_qh[Bn * LDf];                          // q fp16
__device__ __half g_kh[Bn * LDf];                          // k fp16
__device__ __half g_vh[Bn * LDf];                          // v fp16
__device__ __half g_ah[Bn * LDf],     g_al[Bn * LDf];      // attended split
__device__ __half g_p[(size_t)Bn * Hn * Ln * Ln];          // 512MB: exp(S/8) fp16
__device__ float  g_zi[(size_t)Bn * Ln * Ln];              // 64MB: 1/z

// ---------------------------------------------------------------------------
// PTX helpers
// ---------------------------------------------------------------------------
__device__ __forceinline__ unsigned sptr(const void* p) {
    return (unsigned)__cvta_generic_to_shared(p);
}
__device__ __forceinline__ void ldsm_x4(unsigned &r0, unsigned &r1, unsigned &r2, unsigned &r3, unsigned a) {
    asm volatile("ldmatrix.sync.aligned.m8n8.x4.shared.b16 {%0,%1,%2,%3},[%4];\n"
                 : "=r"(r0), "=r"(r1), "=r"(r2), "=r"(r3) : "r"(a));
}
__device__ __forceinline__ void ldsm_x4t(unsigned &r0, unsigned &r1, unsigned &r2, unsigned &r3, unsigned a) {
    asm volatile("ldmatrix.sync.aligned.m8n8.x4.trans.shared.b16 {%0,%1,%2,%3},[%4];\n"
                 : "=r"(r0), "=r"(r1), "=r"(r2), "=r"(r3) : "r"(a));
}
__device__ __forceinline__ void mma16816(float* c, unsigned a0, unsigned a1, unsigned a2, unsigned a3,
                                         unsigned b0, unsigned b1) {
    asm volatile("mma.sync.aligned.m16n8k16.row.col.f32.f16.f16.f32 "
                 "{%0,%1,%2,%3},{%4,%5,%6,%7},{%8,%9},{%0,%1,%2,%3};\n"
                 : "+f"(c[0]), "+f"(c[1]), "+f"(c[2]), "+f"(c[3])
                 : "r"(a0), "r"(a1), "r"(a2), "r"(a3), "r"(b0), "r"(b1));
}
__device__ __forceinline__ void cp16(unsigned d, const void* s) {
    asm volatile("cp.async.cg.shared.global [%0],[%1],16;\n" :: "r"(d), "l"(s) : "memory");
}
__device__ __forceinline__ void cp_commit() {
    asm volatile("cp.async.commit_group;\n" ::: "memory");
}
__device__ __forceinline__ void cp_wait1() {
    asm volatile("cp.async.wait_group 1;\n" ::: "memory");
}

// ---------------------------------------------------------------------------
// FMA-pipe exp: exp(s/8) via exp2 with magic rounding + deg-5 poly.
// ---------------------------------------------------------------------------
__device__ __forceinline__ float fast_exp8(float s) {
    const float MAGIC = 12582912.f;               // 1.5 * 2^23
    float y = __fmul_rn(s, 0.18033688011112042f); // 0.125 * log2(e)
    float t = __fadd_rn(y, MAGIC);
    float f = __fsub_rn(y, __fsub_rn(t, MAGIC));  // frac in [-0.5, 0.5]
    int   e = (__float_as_int(t) - 0x4B400000) << 23;
    float p =              1.3333558e-3f;
    p = fmaf(p, f, 9.6181291e-3f);
    p = fmaf(p, f, 5.5504109e-2f);
    p = fmaf(p, f, 2.4022651e-1f);
    p = fmaf(p, f, 6.9314718e-1f);
    p = fmaf(p, f, 1.0f);
    return __int_as_float(__float_as_int(p) + e);
}

__device__ __forceinline__ void split_store2(__half* Hh, __half* Hl, size_t off, float c0, float c1) {
    __half h0 = __float2half(c0), h1 = __float2half(c1);
    float  r0 = c0 - __half2float(h0), r1 = c1 - __half2float(h1);
    *(__half2*)&Hh[off] = __halves2half2(h0, h1);
    *(__half2*)&Hl[off] = __floats2half2_rn(r0, r1);
}

// ---------------------------------------------------------------------------
// Split fp32 -> fp16.
//   which 0: x    -> g_xh + g_xl  (hi/lo)
//   which 1: wqkv -> g_wqh        (hi only)
//   which 2: wo   -> g_woh        (hi only)
// ---------------------------------------------------------------------------
__global__ void split_kernel(const float* __restrict__ src, int which, int n)
{
    for (int i = blockIdx.x * blockDim.x + threadIdx.x; i < n; i += gridDim.x * blockDim.x) {
        float v = src[i];
        __half h = __float2half(v);
        if (which == 0) {
            g_xh[i] = h;
            g_xl[i] = __float2half(v - __half2float(h));
        } else if (which == 1) {
            g_wqh[i] = h;
        } else {
            g_woh[i] = h;
        }
    }
}

// ---------------------------------------------------------------------------
// Split-precision GEMM: logical K' = 2*1024, segments [Ah|Al] x [Bh|Bh]
// (A exact via hi/lo pair, weights fp16-quantized).
// R10-proven shape: CTA 128x128, 256 thr (2x4 warps), warp tile 64x32, BK=32,
// 3-stage cp.async pipeline, 2 CTAs/SM.
// mode 0: A = x split, B = wqkv; epilogue -> q/k/v fp16.
// mode 1: A = att split, B = wo; epilogue -> fp32 outp.
// ---------------------------------------------------------------------------
#define GS_STAGE (128 * 40 + 32 * 136)   // halfs per stage = 9472

__global__ __launch_bounds__(256, 2) void gemm_split(int mode, float* __restrict__ outp)
{
    extern __shared__ __align__(16) __half gsm[];

    const int t = threadIdx.x, lane = t & 31, wid = t >> 5;
    const int wm = wid >> 2, wn = wid & 3;           // 2 x 4
    const int m0 = blockIdx.y * 128;
    const int n0 = blockIdx.x * 128;

    const __half* __restrict__ Ahp = mode ? g_ah  : g_xh;
    const __half* __restrict__ Alp = mode ? g_al  : g_xl;
    const __half* __restrict__ Bhp = mode ? g_woh : g_wqh;
    const int Nw  = mode ? 1024 : 3072;
    const int NIT = 64;                              // 2 segments * 32 k-steps

    const int arow = t >> 1, acol = (t & 1) * 16;    // A: 128x32 halfs, 2x 16B/thr
    const int brow = t >> 3, bcol = (t & 7) * 16;    // B: 32x128 halfs, 2x 16B/thr
    const size_t aoff = (size_t)(m0 + arow) * 1024 + acol;
    const size_t boff = (size_t)brow * Nw + n0 + bcol;

    auto issue = [&](int it) {
        const int sg = it >> 5;
        const int k0 = (it & 31) * 32;
        const __half* Ap = sg ? Alp : Ahp;
        __half* S  = gsm + (it % 3) * GS_STAGE;
        unsigned da = sptr(S + arow * 40 + acol);
        unsigned db = sptr(S + 128 * 40 + brow * 136 + bcol);
        const __half* ga = Ap + aoff + k0;
        const __half* gb = Bhp + boff + (size_t)k0 * Nw;
        cp16(da,      ga);
        cp16(da + 16, ga + 8);
        cp16(db,      gb);
        cp16(db + 16, gb + 8);
        cp_commit();
    };

    float acc[4][4][4];
#pragma unroll
    for (int i = 0; i < 4; i++)
#pragma unroll
        for (int j = 0; j < 4; j++)
#pragma unroll
            for (int c = 0; c < 4; c++) acc[i][j][c] = 0.f;

    issue(0);
    issue(1);

    for (int it = 0; it < NIT; it++) {
        cp_wait1();
        __syncthreads();
        if (it + 2 < NIT) issue(it + 2);

        __half (*As)[40]  = (__half(*)[40]) (gsm + (it % 3) * GS_STAGE);
        __half (*Bs)[136] = (__half(*)[136])(gsm + (it % 3) * GS_STAGE + 128 * 40);

#pragma unroll
        for (int kk = 0; kk < 2; kk++) {
            const int kb = kk * 16;
            unsigned a[4][4];
#pragma unroll
            for (int mi = 0; mi < 4; mi++)
                ldsm_x4(a[mi][0], a[mi][1], a[mi][2], a[mi][3],
                        sptr(&As[wm * 64 + mi * 16 + (lane & 15)][kb + (lane >> 4) * 8]));
            unsigned bf[4][2];
#pragma unroll
            for (int hb = 0; hb < 2; hb++) {
                unsigned r0, r1, r2, r3;
                ldsm_x4t(r0, r1, r2, r3,
                         sptr(&Bs[kb + (lane & 15)][wn * 32 + hb * 16 + (lane >> 4) * 8]));
                bf[hb * 2][0] = r0;  bf[hb * 2][1] = r1;
                bf[hb * 2 + 1][0] = r2;  bf[hb * 2 + 1][1] = r3;
            }
#pragma unroll
            for (int mi = 0; mi < 4; mi++)
#pragma unroll
                for (int ni = 0; ni < 4; ni++)
                    mma16816(acc[mi][ni], a[mi][0], a[mi][1], a[mi][2], a[mi][3],
                             bf[ni][0], bf[ni][1]);
        }
    }

    // Epilogue
#pragma unroll
    for (int mi = 0; mi < 4; mi++) {
#pragma unroll
        for (int ni = 0; ni < 4; ni++) {
            const int gm = m0 + wm * 64 + mi * 16 + (lane >> 2);
            const int gn = n0 + wn * 32 + ni * 8 + (lane & 3) * 2;
            if (mode == 1) {
                *(float2*)&outp[(size_t)gm * 1024 + gn]       = make_float2(acc[mi][ni][0], acc[mi][ni][1]);
                *(float2*)&outp[(size_t)(gm + 8) * 1024 + gn] = make_float2(acc[mi][ni][2], acc[mi][ni][3]);
            } else {
                const int part = gn >> 10, lc = gn & 1023;
                __half* Hh = (part == 0) ? g_qh : (part == 1) ? g_kh : g_vh;
                *(__half2*)&Hh[(size_t)gm * 1024 + lc] =
                    __floats2half2_rn(acc[mi][ni][0], acc[mi][ni][1]);
                *(__half2*)&Hh[(size_t)(gm + 8) * 1024 + lc] =
                    __floats2half2_rn(acc[mi][ni][2], acc[mi][ni][3]);
            }
        }
    }
}

// ---------------------------------------------------------------------------
// Pass A: per (b, 128-l, 64-m) tile, loop h: S = Qh·Kh (fp16 single pass),
// P = exp(S/8) -> g_p (fp16), z += P; then zinv -> g_zi.
// B-fragments via ldsm_x4 (2 ops per k-step instead of 4 ldsm_x2).
// Dynamic smem: Qh[128][72] + Kh[64][72] = 27648 B.
// ---------------------------------------------------------------------------
__global__ __launch_bounds__(256, 2) void zsum_kernel()
{
    extern __shared__ __half zsm[];
    __half (*Qh)[72] = (__half(*)[72])zsm;
    __half (*Kh)[72] = (__half(*)[72])(zsm + 128 * 72);

    const int t = threadIdx.x, lane = t & 31, wid = t >> 5;
    const int wm = wid >> 1, wn = wid & 1;          // 4 x 2, warp tile 32(l) x 32(m)
    const int m0 = blockIdx.x * 64;
    const int l0 = blockIdx.y * 128;
    const int b  = blockIdx.z;

    float zacc[2][4][4];
#pragma unroll
    for (int i = 0; i < 2; i++)
#pragma unroll
        for (int j = 0; j < 4; j++)
#pragma unroll
            for (int c = 0; c < 4; c++) zacc[i][j][c] = 0.f;

    const int qr = t >> 1, qc = (t & 1) * 32;       // Q tile: 4 uint4/thr
    const int kr = t >> 2, kc = (t & 3) * 16;       // K tile: 2 uint4/thr

    for (int h = 0; h < Hn; h++) {
        const size_t qbase = (size_t)b * LDf + (size_t)h * HSTRd + (size_t)l0 * Kd;
        const size_t kbase = (size_t)b * LDf + (size_t)h * HSTRd + (size_t)m0 * Kd;
        __syncthreads();
#pragma unroll
        for (int i = 0; i < 4; i++) {
            *(uint4*)&Qh[qr][qc + i * 8] = *(const uint4*)(g_qh + qbase + (size_t)qr * Kd + qc + i * 8);
        }
#pragma unroll
        for (int i = 0; i < 2; i++) {
            *(uint4*)&Kh[kr][kc + i * 8] = *(const uint4*)(g_kh + kbase + (size_t)kr * Kd + kc + i * 8);
        }
        __syncthreads();

        float sacc[2][4][4];
#pragma unroll
        for (int i = 0; i < 2; i++)
#pragma unroll
            for (int j = 0; j < 4; j++)
#pragma unroll
                for (int c = 0; c < 4; c++) sacc[i][j][c] = 0.f;

#pragma unroll
        for (int kk = 0; kk < 4; kk++) {
            const int kb = kk * 16;
            unsigned a[2][4];
#pragma unroll
            for (int mi = 0; mi < 2; mi++)
                ldsm_x4(a[mi][0], a[mi][1], a[mi][2], a[mi][3],
                        sptr(&Qh[wm * 32 + mi * 16 + (lane & 15)][kb + (lane >> 4) * 8]));
            // B fragments: one ldsm_x4 covers two n-groups (16 m-rows) x k16
            unsigned bf[4][2];
#pragma unroll
            for (int hb = 0; hb < 2; hb++) {
                unsigned r0, r1, r2, r3;
                ldsm_x4(r0, r1, r2, r3,
                        sptr(&Kh[wn * 32 + hb * 16 + (lane & 15)][kb + (lane >> 4) * 8]));
                bf[hb * 2][0] = r0;  bf[hb * 2][1] = r2;   // n-group hb*2   (klow, khi)
                bf[hb * 2 + 1][0] = r1;  bf[hb * 2 + 1][1] = r3; // n-group hb*2+1
            }
#pragma unroll
            for (int mi = 0; mi < 2; mi++)
#pragma unroll
                for (int ni = 0; ni < 4; ni++)
                    mma16816(sacc[mi][ni], a[mi][0], a[mi][1], a[mi][2], a[mi][3],
                             bf[ni][0], bf[ni][1]);
        }

        // exp (FMA-pipe poly), accumulate z, write P
        const size_t pbase = (size_t)(b * Hn + h) * Ln * Ln;
#pragma unroll
        for (int mi = 0; mi < 2; mi++) {
#pragma unroll
            for (int ni = 0; ni < 4; ni++) {
                const int gl = l0 + wm * 32 + mi * 16 + (lane >> 2);
                const int gm = m0 + wn * 32 + ni * 8 + (lane & 3) * 2;
                float p0 = fast_exp8(sacc[mi][ni][0]);
                float p1 = fast_exp8(sacc[mi][ni][1]);
                float p2 = fast_exp8(sacc[mi][ni][2]);
                float p3 = fast_exp8(sacc[mi][ni][3]);
                zacc[mi][ni][0] += p0; zacc[mi][ni][1] += p1;
                zacc[mi][ni][2] += p2; zacc[mi][ni][3] += p3;
                *(__half2*)&g_p[pbase + (size_t)gl * Ln + gm]       = __floats2half2_rn(p0, p1);
                *(__half2*)&g_p[pbase + (size_t)(gl + 8) * Ln + gm] = __floats2half2_rn(p2, p3);
            }
        }
    }

    // zinv
#pragma unroll
    for (int mi = 0; mi < 2; mi++) {
#pragma unroll
        for (int ni = 0; ni < 4; ni++) {
            const int gl = l0 + wm * 32 + mi * 16 + (lane >> 2);
            const int gm = m0 + wn * 32 + ni * 8 + (lane & 3) * 2;
            *(float2*)&g_zi[((size_t)b * Ln + gl) * Ln + gm] =
                make_float2(__fdividef(1.f, zacc[mi][ni][0]), __fdividef(1.f, zacc[mi][ni][1]));
            *(float2*)&g_zi[((size_t)b * Ln + gl + 8) * Ln + gm] =
                make_float2(__fdividef(1.f, zacc[mi][ni][2]), __fdividef(1.f, zacc[mi][ni][3]));
        }
    }
}

// ---------------------------------------------------------------------------
// Pass B: O[128 l, 64 kd] = sum_m (P * zinv) @ Vh  per (b, h, l-tile).
// Static smem: Ps[128][72] + Vhs[64][72] = 27648 B.
// ---------------------------------------------------------------------------
__global__ __launch_bounds__(256, 2) void apv_kernel()
{
    __shared__ __half Ps[128][72];
    __shared__ __half Vhs[64][72];

    const int t = threadIdx.x, lane = t & 31, wid = t >> 5;
    const int wm = wid >> 1, wn = wid & 1;          // 4 x 2, warp tile 32(l) x 32(kd)
    const int l0 = blockIdx.x * 128;
    const int h  = blockIdx.y;
    const int b  = blockIdx.z;

    float acc[2][4][4];
#pragma unroll
    for (int i = 0; i < 2; i++)
#pragma unroll
        for (int j = 0; j < 4; j++)
#pragma unroll
            for (int c = 0; c < 4; c++) acc[i][j][c] = 0.f;

    const size_t vbase = (size_t)b * LDf + (size_t)h * HSTRd;
    const size_t pbase = (size_t)(b * Hn + h) * Ln * Ln + (size_t)l0 * Ln;
    const size_t zbase = ((size_t)b * Ln + l0) * Ln;

    const int pr = t >> 1, pc = (t & 1) * 32;       // P/z rows
    const int vr = t >> 2, vc = (t & 3) * 16;       // V rows

    for (int m0 = 0; m0 < Ln; m0 += 64) {
        __syncthreads();
#pragma unroll
        for (int i = 0; i < 4; i++) {
            const size_t po = (size_t)pr * Ln + m0 + pc + i * 8;
            uint4 pv = *(const uint4*)(g_p + pbase + po);
            float4 za = *(const float4*)(g_zi + zbase + po);
            float4 zb = *(const float4*)(g_zi + zbase + po + 4);
            __half2* ph = (__half2*)&pv;
            uint4 ov;
            __half2* po2 = (__half2*)&ov;
            float2 f;
            f = __half22float2(ph[0]); po2[0] = __floats2half2_rn(f.x * za.x, f.y * za.y);
            f = __half22float2(ph[1]); po2[1] = __floats2half2_rn(f.x * za.z, f.y * za.w);
            f = __half22float2(ph[2]); po2[2] = __floats2half2_rn(f.x * zb.x, f.y * zb.y);
            f = __half22float2(ph[3]); po2[3] = __floats2half2_rn(f.x * zb.z, f.y * zb.w);
            *(uint4*)&Ps[pr][pc + i * 8] = ov;
        }
#pragma unroll
        for (int i = 0; i < 2; i++) {
            *(uint4*)&Vhs[vr][vc + i * 8] = *(const uint4*)(g_vh + vbase + (size_t)(m0 + vr) * Kd + vc + i * 8);
        }
        __syncthreads();

#pragma unroll
        for (int kk = 0; kk < 4; kk++) {
            const int kb = kk * 16;
            unsigned a[2][4];
#pragma unroll
            for (int mi = 0; mi < 2; mi++)
                ldsm_x4(a[mi][0], a[mi][1], a[mi][2], a[mi][3],
                        sptr(&Ps[wm * 32 + mi * 16 + (lane & 15)][kb + (lane >> 4) * 8]));
            unsigned bh[4][2];
#pragma unroll
            for (int hb = 0; hb < 2; hb++) {
                unsigned r0, r1, r2, r3;
                ldsm_x4t(r0, r1, r2, r3,
                         sptr(&Vhs[kb + (lane & 15)][wn * 32 + hb * 16 + (lane >> 4) * 8]));
                bh[hb * 2][0] = r0; bh[hb * 2][1] = r1; bh[hb * 2 + 1][0] = r2; bh[hb * 2 + 1][1] = r3;
            }
#pragma unroll
            for (int mi = 0; mi < 2; mi++)
#pragma unroll
                for (int ni = 0; ni < 4; ni++)
                    mma16816(acc[mi][ni], a[mi][0], a[mi][1], a[mi][2], a[mi][3], bh[ni][0], bh[ni][1]);
        }
    }

    // Epilogue: split-write attended in concatted layout [b, l, h*64 + kd]
#pragma unroll
    for (int mi = 0; mi < 2; mi++) {
#pragma unroll
        for (int ni = 0; ni < 4; ni++) {
            const int gl = l0 + wm * 32 + mi * 16 + (lane >> 2);
            const int gc = h * Kd + wn * 32 + ni * 8 + (lane & 3) * 2;
            split_store2(g_ah, g_al, ((size_t)b * Ln + gl) * 1024 + gc,
                         acc[mi][ni][0], acc[mi][ni][1]);
            split_store2(g_ah, g_al, ((size_t)b * Ln + gl + 8) * 1024 + gc,
                         acc[mi][ni][2], acc[mi][ni][3]);
        }
    }
}

// ---------------------------------------------------------------------------
// Launch
// ---------------------------------------------------------------------------
extern "C" void kernel_launch(void* const* d_in, const int* in_sizes, int n_in,
                              void* d_out, int out_size)
{
    const float* x    = (const float*)d_in[0];
    const float* wqkv = (const float*)d_in[1];
    const float* wo   = (const float*)d_in[2];
    float* out = (float*)d_out;

    cudaFuncSetAttribute(gemm_split, cudaFuncAttributeMaxDynamicSharedMemorySize, GS_STAGE * 3 * 2);
    cudaFuncSetAttribute(zsum_kernel, cudaFuncAttributeMaxDynamicSharedMemorySize, 27648);

    // 0) fp32 -> fp16 splits
    split_kernel<<<4096, 256>>>(x,    0, Bn * LDf);
    split_kernel<<<2048, 256>>>(wqkv, 1, Dn * 3 * Dn);
    split_kernel<<<1024, 256>>>(wo,   2, Dn * Dn);

    // 1) QKV projection (2-pass split GEMM, 128x128 CTA, 2 CTA/SM) -> q/k/v fp16
    gemm_split<<<dim3(24, 64), 256, GS_STAGE * 3 * 2>>>(0, nullptr);

    // 2) Pass A: P = exp(QK^T/8) -> g_p,  zinv over head axis -> g_zi
    zsum_kernel<<<dim3(32, 16, 4), 256, 27648>>>();

    // 3) Pass B: O = (P * zinv) @ Vh -> g_att hi+lo (concatted layout)
    apv_kernel<<<dim3(16, 16, 4), 256>>>();

    // 4) Output projection (2-pass split GEMM: attended exact, wo fp16) -> d_out
    gemm_split<<<dim3(8, 64), 256, GS_STAGE * 3 * 2>>>(1, out);
}

// round 14
// speedup vs baseline: 1.4290x; 1.3209x over previous
#include <cuda_runtime.h>
#include <cuda_fp16.h>

// ---------------------------------------------------------------------------
// Problem constants
// ---------------------------------------------------------------------------
#define Bn   4
#define Ln   2048
#define Dn   1024
#define Hn   16
#define Kd   64
#define LDf  (Ln * Dn)       // 2097152 floats per batch
#define HSTRd (Ln * Kd)      // 131072: contiguous per-head [2048,64] block

// P / zinv fragment-tile geometry: tiles of 128 l x 64 m, 8192 halfs each.
// Within-tile offset (halfs): ((((wm*2+wn)*2+mi)*2+rg)*32 + lane) * 8
//   wm: l-strip (4 x 32), wn: m-strip (2 x 32), mi: 16-row group, rg: r vs r+8,
//   lane: mma lane, 8 halfs = 4 half2 (ni=0..3 -> m = wn*32 + ni*8 + 2*(lane&3)).
#define PTILE 8192

// ---------------------------------------------------------------------------
// Scratch (static __device__ — allocation-free rule)
// ---------------------------------------------------------------------------
__device__ __align__(16) __half g_xh[Bn * LDf],     g_xl[Bn * LDf];  // x split
__device__ __align__(16) __half g_wqh[Dn * 3 * Dn];                  // wqkv fp16
__device__ __align__(16) __half g_woh[Dn * Dn];                      // wo fp16
__device__ __align__(16) __half g_qh[Bn * LDf];                      // q fp16
__device__ __align__(16) __half g_kh[Bn * LDf];                      // k fp16
__device__ __align__(16) __half g_vh[Bn * LDf];                      // v fp16
__device__ __align__(16) __half g_ah[Bn * LDf], g_al[Bn * LDf];      // attended split
__device__ __align__(16) __half g_p[(size_t)Bn * Hn * Ln * Ln];      // 512MB: P fragments
__device__ __align__(16) __half g_zif[(size_t)Bn * 16 * 32 * PTILE]; // 33.5MB: zinv fragments

// ---------------------------------------------------------------------------
// PTX helpers
// ---------------------------------------------------------------------------
__device__ __forceinline__ unsigned sptr(const void* p) {
    return (unsigned)__cvta_generic_to_shared(p);
}
__device__ __forceinline__ void ldsm_x4(unsigned &r0, unsigned &r1, unsigned &r2, unsigned &r3, unsigned a) {
    asm volatile("ldmatrix.sync.aligned.m8n8.x4.shared.b16 {%0,%1,%2,%3},[%4];\n"
                 : "=r"(r0), "=r"(r1), "=r"(r2), "=r"(r3) : "r"(a));
}
__device__ __forceinline__ void ldsm_x4t(unsigned &r0, unsigned &r1, unsigned &r2, unsigned &r3, unsigned a) {
    asm volatile("ldmatrix.sync.aligned.m8n8.x4.trans.shared.b16 {%0,%1,%2,%3},[%4];\n"
                 : "=r"(r0), "=r"(r1), "=r"(r2), "=r"(r3) : "r"(a));
}
__device__ __forceinline__ void mma16816(float* c, unsigned a0, unsigned a1, unsigned a2, unsigned a3,
                                         unsigned b0, unsigned b1) {
    asm volatile("mma.sync.aligned.m16n8k16.row.col.f32.f16.f16.f32 "
                 "{%0,%1,%2,%3},{%4,%5,%6,%7},{%8,%9},{%0,%1,%2,%3};\n"
                 : "+f"(c[0]), "+f"(c[1]), "+f"(c[2]), "+f"(c[3])
                 : "r"(a0), "r"(a1), "r"(a2), "r"(a3), "r"(b0), "r"(b1));
}
__device__ __forceinline__ void cp16(unsigned d, const void* s) {
    asm volatile("cp.async.cg.shared.global [%0],[%1],16;\n" :: "r"(d), "l"(s) : "memory");
}
__device__ __forceinline__ void cp_commit() {
    asm volatile("cp.async.commit_group;\n" ::: "memory");
}
__device__ __forceinline__ void cp_wait1() {
    asm volatile("cp.async.wait_group 1;\n" ::: "memory");
}

__device__ __forceinline__ void split_store2(__half* Hh, __half* Hl, size_t off, float c0, float c1) {
    __half h0 = __float2half(c0), h1 = __float2half(c1);
    float  r0 = c0 - __half2float(h0), r1 = c1 - __half2float(h1);
    *(__half2*)&Hh[off] = __halves2half2(h0, h1);
    *(__half2*)&Hl[off] = __floats2half2_rn(r0, r1);
}

// ---------------------------------------------------------------------------
// Split fp32 -> fp16.
// ---------------------------------------------------------------------------
__global__ void split_kernel(const float* __restrict__ src, int which, int n)
{
    for (int i = blockIdx.x * blockDim.x + threadIdx.x; i < n; i += gridDim.x * blockDim.x) {
        float v = src[i];
        __half h = __float2half(v);
        if (which == 0) {
            g_xh[i] = h;
            g_xl[i] = __float2half(v - __half2float(h));
        } else if (which == 1) {
            g_wqh[i] = h;
        } else {
            g_woh[i] = h;
        }
    }
}

// ---------------------------------------------------------------------------
// Split-precision GEMM (R13-proven): K' = 2*1024, [Ah|Al] x [Bh|Bh].
// CTA 128x128, 256 thr (2x4 warps), warp tile 64x32, BK=32, 3-stage cp.async.
// ---------------------------------------------------------------------------
#define GS_STAGE (128 * 40 + 32 * 136)   // halfs per stage = 9472

__global__ __launch_bounds__(256, 2) void gemm_split(int mode, float* __restrict__ outp)
{
    extern __shared__ __align__(16) __half gsm[];

    const int t = threadIdx.x, lane = t & 31, wid = t >> 5;
    const int wm = wid >> 2, wn = wid & 3;           // 2 x 4
    const int m0 = blockIdx.y * 128;
    const int n0 = blockIdx.x * 128;

    const __half* __restrict__ Ahp = mode ? g_ah  : g_xh;
    const __half* __restrict__ Alp = mode ? g_al  : g_xl;
    const __half* __restrict__ Bhp = mode ? g_woh : g_wqh;
    const int Nw  = mode ? 1024 : 3072;
    const int NIT = 64;

    const int arow = t >> 1, acol = (t & 1) * 16;
    const int brow = t >> 3, bcol = (t & 7) * 16;
    const size_t aoff = (size_t)(m0 + arow) * 1024 + acol;
    const size_t boff = (size_t)brow * Nw + n0 + bcol;

    auto issue = [&](int it) {
        const int sg = it >> 5;
        const int k0 = (it & 31) * 32;
        const __half* Ap = sg ? Alp : Ahp;
        __half* S  = gsm + (it % 3) * GS_STAGE;
        unsigned da = sptr(S + arow * 40 + acol);
        unsigned db = sptr(S + 128 * 40 + brow * 136 + bcol);
        const __half* ga = Ap + aoff + k0;
        const __half* gb = Bhp + boff + (size_t)k0 * Nw;
        cp16(da,      ga);
        cp16(da + 16, ga + 8);
        cp16(db,      gb);
        cp16(db + 16, gb + 8);
        cp_commit();
    };

    float acc[4][4][4];
#pragma unroll
    for (int i = 0; i < 4; i++)
#pragma unroll
        for (int j = 0; j < 4; j++)
#pragma unroll
            for (int c = 0; c < 4; c++) acc[i][j][c] = 0.f;

    issue(0);
    issue(1);

    for (int it = 0; it < NIT; it++) {
        cp_wait1();
        __syncthreads();
        if (it + 2 < NIT) issue(it + 2);

        __half (*As)[40]  = (__half(*)[40]) (gsm + (it % 3) * GS_STAGE);
        __half (*Bs)[136] = (__half(*)[136])(gsm + (it % 3) * GS_STAGE + 128 * 40);

#pragma unroll
        for (int kk = 0; kk < 2; kk++) {
            const int kb = kk * 16;
            unsigned a[4][4];
#pragma unroll
            for (int mi = 0; mi < 4; mi++)
                ldsm_x4(a[mi][0], a[mi][1], a[mi][2], a[mi][3],
                        sptr(&As[wm * 64 + mi * 16 + (lane & 15)][kb + (lane >> 4) * 8]));
            unsigned bf[4][2];
#pragma unroll
            for (int hb = 0; hb < 2; hb++) {
                unsigned r0, r1, r2, r3;
                ldsm_x4t(r0, r1, r2, r3,
                         sptr(&Bs[kb + (lane & 15)][wn * 32 + hb * 16 + (lane >> 4) * 8]));
                bf[hb * 2][0] = r0;  bf[hb * 2][1] = r1;
                bf[hb * 2 + 1][0] = r2;  bf[hb * 2 + 1][1] = r3;
            }
#pragma unroll
            for (int mi = 0; mi < 4; mi++)
#pragma unroll
                for (int ni = 0; ni < 4; ni++)
                    mma16816(acc[mi][ni], a[mi][0], a[mi][1], a[mi][2], a[mi][3],
                             bf[ni][0], bf[ni][1]);
        }
    }

#pragma unroll
    for (int mi = 0; mi < 4; mi++) {
#pragma unroll
        for (int ni = 0; ni < 4; ni++) {
            const int gm = m0 + wm * 64 + mi * 16 + (lane >> 2);
            const int gn = n0 + wn * 32 + ni * 8 + (lane & 3) * 2;
            if (mode == 1) {
                *(float2*)&outp[(size_t)gm * 1024 + gn]       = make_float2(acc[mi][ni][0], acc[mi][ni][1]);
                *(float2*)&outp[(size_t)(gm + 8) * 1024 + gn] = make_float2(acc[mi][ni][2], acc[mi][ni][3]);
            } else {
                const int part = gn >> 10, lc = gn & 1023;
                __half* Hh = (part == 0) ? g_qh : (part == 1) ? g_kh : g_vh;
                *(__half2*)&Hh[(size_t)gm * 1024 + lc] =
                    __floats2half2_rn(acc[mi][ni][0], acc[mi][ni][1]);
                *(__half2*)&Hh[(size_t)(gm + 8) * 1024 + lc] =
                    __floats2half2_rn(acc[mi][ni][2], acc[mi][ni][3]);
            }
        }
    }
}

// ---------------------------------------------------------------------------
// Pass A: per (b, 128-l, 64-m) tile, loop h: S = Qh·Kh, P = exp(S/8) stored as
// mma C-FRAGMENTS (coalesced STG.128), z accumulated over heads; zinv stored
// as packed half2 fragments. Dynamic smem: Qh[128][72] + Kh[64][72] = 27648 B.
// ---------------------------------------------------------------------------
__global__ __launch_bounds__(256, 2) void zsum_kernel()
{
    extern __shared__ __half zsm[];
    __half (*Qh)[72] = (__half(*)[72])zsm;
    __half (*Kh)[72] = (__half(*)[72])(zsm + 128 * 72);

    const int t = threadIdx.x, lane = t & 31, wid = t >> 5;
    const int wm = wid >> 1, wn = wid & 1;          // 4 x 2, warp tile 32(l) x 32(m)
    const int mt = blockIdx.x;                      // m-tile (64 wide)
    const int lt = blockIdx.y;                      // l-tile (128 wide)
    const int m0 = mt * 64;
    const int l0 = lt * 128;
    const int b  = blockIdx.z;

    // fragment base offset for this thread (rg = 0), in halfs
    const int fbase0 = ((((wm * 2 + wn) * 2) * 2) * 32 + lane) * 8;  // mi=0, rg=0
    // per-mi stride = 2*32*8 = 512 halfs, per-rg stride = 32*8 = 256 halfs

    float zacc[2][4][4];
#pragma unroll
    for (int i = 0; i < 2; i++)
#pragma unroll
        for (int j = 0; j < 4; j++)
#pragma unroll
            for (int c = 0; c < 4; c++) zacc[i][j][c] = 0.f;

    const int qr = t >> 1, qc = (t & 1) * 32;
    const int kr = t >> 2, kc = (t & 3) * 16;

    for (int h = 0; h < Hn; h++) {
        const size_t qbase = (size_t)b * LDf + (size_t)h * HSTRd + (size_t)l0 * Kd;
        const size_t kbase = (size_t)b * LDf + (size_t)h * HSTRd + (size_t)m0 * Kd;
        __syncthreads();
#pragma unroll
        for (int i = 0; i < 4; i++) {
            *(uint4*)&Qh[qr][qc + i * 8] = *(const uint4*)(g_qh + qbase + (size_t)qr * Kd + qc + i * 8);
        }
#pragma unroll
        for (int i = 0; i < 2; i++) {
            *(uint4*)&Kh[kr][kc + i * 8] = *(const uint4*)(g_kh + kbase + (size_t)kr * Kd + kc + i * 8);
        }
        __syncthreads();

        float sacc[2][4][4];
#pragma unroll
        for (int i = 0; i < 2; i++)
#pragma unroll
            for (int j = 0; j < 4; j++)
#pragma unroll
                for (int c = 0; c < 4; c++) sacc[i][j][c] = 0.f;

#pragma unroll
        for (int kk = 0; kk < 4; kk++) {
            const int kb = kk * 16;
            unsigned a[2][4];
#pragma unroll
            for (int mi = 0; mi < 2; mi++)
                ldsm_x4(a[mi][0], a[mi][1], a[mi][2], a[mi][3],
                        sptr(&Qh[wm * 32 + mi * 16 + (lane & 15)][kb + (lane >> 4) * 8]));
            unsigned bf[4][2];
#pragma unroll
            for (int hb = 0; hb < 2; hb++) {
                unsigned r0, r1, r2, r3;
                ldsm_x4(r0, r1, r2, r3,
                        sptr(&Kh[wn * 32 + hb * 16 + (lane & 15)][kb + (lane >> 4) * 8]));
                bf[hb * 2][0] = r0;  bf[hb * 2][1] = r2;
                bf[hb * 2 + 1][0] = r1;  bf[hb * 2 + 1][1] = r3;
            }
#pragma unroll
            for (int mi = 0; mi < 2; mi++)
#pragma unroll
                for (int ni = 0; ni < 4; ni++)
                    mma16816(sacc[mi][ni], a[mi][0], a[mi][1], a[mi][2], a[mi][3],
                             bf[ni][0], bf[ni][1]);
        }

        // exp (MUFU), accumulate z, write P as C-fragments (coalesced STG.128)
        const size_t pb = (((size_t)(b * Hn + h) * 16 + lt) * 32 + mt) * PTILE;
#pragma unroll
        for (int mi = 0; mi < 2; mi++) {
            uint4 U0, U1;
            __half2* u0 = (__half2*)&U0;
            __half2* u1 = (__half2*)&U1;
#pragma unroll
            for (int ni = 0; ni < 4; ni++) {
                float p0 = __expf(sacc[mi][ni][0] * 0.125f);
                float p1 = __expf(sacc[mi][ni][1] * 0.125f);
                float p2 = __expf(sacc[mi][ni][2] * 0.125f);
                float p3 = __expf(sacc[mi][ni][3] * 0.125f);
                zacc[mi][ni][0] += p0; zacc[mi][ni][1] += p1;
                zacc[mi][ni][2] += p2; zacc[mi][ni][3] += p3;
                u0[ni] = __floats2half2_rn(p0, p1);
                u1[ni] = __floats2half2_rn(p2, p3);
            }
            const size_t o = pb + fbase0 + mi * 512;
            *(uint4*)(g_p + o)       = U0;   // rg = 0
            *(uint4*)(g_p + o + 256) = U1;   // rg = 1
        }
    }

    // zinv as packed half2 fragments
    const size_t zb = (((size_t)b * 16 + lt) * 32 + mt) * PTILE;
#pragma unroll
    for (int mi = 0; mi < 2; mi++) {
        uint4 U0, U1;
        __half2* u0 = (__half2*)&U0;
        __half2* u1 = (__half2*)&U1;
#pragma unroll
        for (int ni = 0; ni < 4; ni++) {
            u0[ni] = __floats2half2_rn(__fdividef(1.f, zacc[mi][ni][0]),
                                       __fdividef(1.f, zacc[mi][ni][1]));
            u1[ni] = __floats2half2_rn(__fdividef(1.f, zacc[mi][ni][2]),
                                       __fdividef(1.f, zacc[mi][ni][3]));
        }
        const size_t o = zb + fbase0 + mi * 512;
        *(uint4*)(g_zif + o)       = U0;
        *(uint4*)(g_zif + o + 256) = U1;
    }
}

// ---------------------------------------------------------------------------
// Pass B: O[128 l, 64 kd] = sum_m (P * zinv) @ Vh per (b, h, l-tile).
// P and zinv loaded as fragments straight into mma A-operands (no smem
// staging, no ldmatrix for P): a = hmul2(P_frag, zinv_frag).
// Static smem: Vhs[64][72] = 9216 B.
// ---------------------------------------------------------------------------
__global__ __launch_bounds__(256, 2) void apv_kernel()
{
    __shared__ __half Vhs[64][72];

    const int t = threadIdx.x, lane = t & 31, wid = t >> 5;
    const int wm = wid >> 1, wn = wid & 1;          // 4 x 2, warp tile 32(l) x 32(kd)
    const int lt = blockIdx.x;
    const int h  = blockIdx.y;
    const int b  = blockIdx.z;
    const int l0 = lt * 128;

    float acc[2][4][4];
#pragma unroll
    for (int i = 0; i < 2; i++)
#pragma unroll
        for (int j = 0; j < 4; j++)
#pragma unroll
            for (int c = 0; c < 4; c++) acc[i][j][c] = 0.f;

    const size_t vbase = (size_t)b * LDf + (size_t)h * HSTRd;
    const size_t pbase = ((size_t)(b * Hn + h) * 16 + lt) * 32 * PTILE;
    const size_t zbase = ((size_t)b * 16 + lt) * 32 * PTILE;

    const int vr = t >> 2, vc = (t & 3) * 16;       // V staging rows

    for (int mt = 0; mt < 32; mt++) {
        const int m0 = mt * 64;
        __syncthreads();
#pragma unroll
        for (int i = 0; i < 2; i++) {
            *(uint4*)&Vhs[vr][vc + i * 8] = *(const uint4*)(g_vh + vbase + (size_t)(m0 + vr) * Kd + vc + i * 8);
        }
        __syncthreads();

        const size_t pb = pbase + (size_t)mt * PTILE;
        const size_t zb = zbase + (size_t)mt * PTILE;

#pragma unroll
        for (int j = 0; j < 2; j++) {               // source m-strip (wn_src)
            // load + normalize P fragments for this strip: M[mi][rg]
            uint4 M[2][2];
#pragma unroll
            for (int mi = 0; mi < 2; mi++)
#pragma unroll
                for (int rg = 0; rg < 2; rg++) {
                    const size_t o = (size_t)((((((wm * 2 + j) * 2 + mi) * 2 + rg) * 32) + lane) * 8);
                    uint4 P = *(const uint4*)(g_p + pb + o);
                    uint4 Z = *(const uint4*)(g_zif + zb + o);
                    const __half2* ph = (const __half2*)&P;
                    const __half2* zh = (const __half2*)&Z;
                    __half2* mh = (__half2*)&M[mi][rg];
                    mh[0] = __hmul2(ph[0], zh[0]);
                    mh[1] = __hmul2(ph[1], zh[1]);
                    mh[2] = __hmul2(ph[2], zh[2]);
                    mh[3] = __hmul2(ph[3], zh[3]);
                }

#pragma unroll
            for (int kq = 0; kq < 2; kq++) {
                const int kk = j * 2 + kq;
                const int kb = kk * 16;
                const int nb = kq * 2;
                unsigned bh[4][2];
#pragma unroll
                for (int hb = 0; hb < 2; hb++) {
                    unsigned r0, r1, r2, r3;
                    ldsm_x4t(r0, r1, r2, r3,
                             sptr(&Vhs[kb + (lane & 15)][wn * 32 + hb * 16 + (lane >> 4) * 8]));
                    bh[hb * 2][0] = r0; bh[hb * 2][1] = r1;
                    bh[hb * 2 + 1][0] = r2; bh[hb * 2 + 1][1] = r3;
                }
#pragma unroll
                for (int mi = 0; mi < 2; mi++) {
                    const unsigned* m0w = (const unsigned*)&M[mi][0];
                    const unsigned* m1w = (const unsigned*)&M[mi][1];
                    const unsigned a0 = m0w[nb], a2 = m0w[nb + 1];
                    const unsigned a1 = m1w[nb], a3 = m1w[nb + 1];
#pragma unroll
                    for (int ni = 0; ni < 4; ni++)
                        mma16816(acc[mi][ni], a0, a1, a2, a3, bh[ni][0], bh[ni][1]);
                }
            }
        }
    }

    // Epilogue: split-write attended in concatted layout [b, l, h*64 + kd]
#pragma unroll
    for (int mi = 0; mi < 2; mi++) {
#pragma unroll
        for (int ni = 0; ni < 4; ni++) {
            const int gl = l0 + wm * 32 + mi * 16 + (lane >> 2);
            const int gc = h * Kd + wn * 32 + ni * 8 + (lane & 3) * 2;
            split_store2(g_ah, g_al, ((size_t)b * Ln + gl) * 1024 + gc,
                         acc[mi][ni][0], acc[mi][ni][1]);
            split_store2(g_ah, g_al, ((size_t)b * Ln + gl + 8) * 1024 + gc,
                         acc[mi][ni][2], acc[mi][ni][3]);
        }
    }
}

// ---------------------------------------------------------------------------
// Launch
// ---------------------------------------------------------------------------
extern "C" void kernel_launch(void* const* d_in, const int* in_sizes, int n_in,
                              void* d_out, int out_size)
{
    const float* x    = (const float*)d_in[0];
    const float* wqkv = (const float*)d_in[1];
    const float* wo   = (const float*)d_in[2];
    float* out = (float*)d_out;

    cudaFuncSetAttribute(gemm_split, cudaFuncAttributeMaxDynamicSharedMemorySize, GS_STAGE * 3 * 2);
    cudaFuncSetAttribute(zsum_kernel, cudaFuncAttributeMaxDynamicSharedMemorySize, 27648);

    // 0) fp32 -> fp16 splits
    split_kernel<<<4096, 256>>>(x,    0, Bn * LDf);
    split_kernel<<<2048, 256>>>(wqkv, 1, Dn * 3 * Dn);
    split_kernel<<<1024, 256>>>(wo,   2, Dn * Dn);

    // 1) QKV projection (2-pass split GEMM) -> q/k/v fp16
    gemm_split<<<dim3(24, 64), 256, GS_STAGE * 3 * 2>>>(0, nullptr);

    // 2) Pass A: P fragments + zinv fragments
    zsum_kernel<<<dim3(32, 16, 4), 256, 27648>>>();

    // 3) Pass B: O = (P * zinv) @ Vh via direct fragment loads
    apv_kernel<<<dim3(16, 16, 4), 256>>>();

    // 4) Output projection (2-pass split GEMM) -> d_out
    gemm_split<<<dim3(8, 64), 256, GS_STAGE * 3 * 2>>>(1, out);
}

// round 15
// speedup vs baseline: 1.8982x; 1.3284x over previous
#include <cuda_runtime.h>
#include <cuda_fp16.h>

// ---------------------------------------------------------------------------
// Problem constants
// ---------------------------------------------------------------------------
#define Bn   4
#define Ln   2048
#define Dn   1024
#define Hn   16
#define Kd   64
#define LDf  (Ln * Dn)       // 2097152 floats per batch
#define HSTRd (Ln * Kd)      // 131072: contiguous per-head [2048,64] block

// P / zinv fragment-tile geometry: tiles of 128 l x 64 m, 8192 halfs each.
#define PTILE 8192

// ---------------------------------------------------------------------------
// Scratch (static __device__ — allocation-free rule)
// ---------------------------------------------------------------------------
__device__ __align__(16) __half g_xh[Bn * LDf];                      // x fp16
__device__ __align__(16) __half g_wqh[Dn * 3 * Dn];                  // wqkv fp16
__device__ __align__(16) __half g_woh[Dn * Dn];                      // wo fp16
__device__ __align__(16) __half g_qh[Bn * LDf];                      // q fp16
__device__ __align__(16) __half g_kh[Bn * LDf];                      // k fp16
__device__ __align__(16) __half g_vh[Bn * LDf];                      // v fp16
__device__ __align__(16) __half g_ah[Bn * LDf];                      // attended fp16
__device__ __align__(16) __half g_p[(size_t)Bn * Hn * Ln * Ln];      // 512MB: P fragments
__device__ __align__(16) __half g_zif[(size_t)Bn * 16 * 32 * PTILE]; // 33.5MB: zinv fragments

// ---------------------------------------------------------------------------
// PTX helpers
// ---------------------------------------------------------------------------
__device__ __forceinline__ unsigned sptr(const void* p) {
    return (unsigned)__cvta_generic_to_shared(p);
}
__device__ __forceinline__ void ldsm_x4(unsigned &r0, unsigned &r1, unsigned &r2, unsigned &r3, unsigned a) {
    asm volatile("ldmatrix.sync.aligned.m8n8.x4.shared.b16 {%0,%1,%2,%3},[%4];\n"
                 : "=r"(r0), "=r"(r1), "=r"(r2), "=r"(r3) : "r"(a));
}
__device__ __forceinline__ void ldsm_x4t(unsigned &r0, unsigned &r1, unsigned &r2, unsigned &r3, unsigned a) {
    asm volatile("ldmatrix.sync.aligned.m8n8.x4.trans.shared.b16 {%0,%1,%2,%3},[%4];\n"
                 : "=r"(r0), "=r"(r1), "=r"(r2), "=r"(r3) : "r"(a));
}
__device__ __forceinline__ void mma16816(float* c, unsigned a0, unsigned a1, unsigned a2, unsigned a3,
                                         unsigned b0, unsigned b1) {
    asm volatile("mma.sync.aligned.m16n8k16.row.col.f32.f16.f16.f32 "
                 "{%0,%1,%2,%3},{%4,%5,%6,%7},{%8,%9},{%0,%1,%2,%3};\n"
                 : "+f"(c[0]), "+f"(c[1]), "+f"(c[2]), "+f"(c[3])
                 : "r"(a0), "r"(a1), "r"(a2), "r"(a3), "r"(b0), "r"(b1));
}
__device__ __forceinline__ void cp16(unsigned d, const void* s) {
    asm volatile("cp.async.cg.shared.global [%0],[%1],16;\n" :: "r"(d), "l"(s) : "memory");
}
__device__ __forceinline__ void cp_commit() {
    asm volatile("cp.async.commit_group;\n" ::: "memory");
}
__device__ __forceinline__ void cp_wait1() {
    asm volatile("cp.async.wait_group 1;\n" ::: "memory");
}

// ---------------------------------------------------------------------------
// Split fp32 -> fp16 (hi only).  which: 0=x, 1=wqkv, 2=wo
// ---------------------------------------------------------------------------
__global__ void split_kernel(const float* __restrict__ src, int which, int n)
{
    __half* dst = (which == 0) ? g_xh : (which == 1) ? g_wqh : g_woh;
    for (int i = blockIdx.x * blockDim.x + threadIdx.x; i < n; i += gridDim.x * blockDim.x) {
        dst[i] = __float2half(src[i]);
    }
}

// ---------------------------------------------------------------------------
// fp16 GEMM (single pass, K = 1024).
// CTA 128x128, 256 thr (2x4 warps), warp tile 64x32, BK=32, 3-stage cp.async.
// mode 0: A = x, B = wqkv; epilogue -> q/k/v fp16.
// mode 1: A = att, B = wo; epilogue -> fp32 outp.
// ---------------------------------------------------------------------------
#define GS_STAGE (128 * 40 + 32 * 136)   // halfs per stage = 9472

__global__ __launch_bounds__(256, 2) void gemm_split(int mode, float* __restrict__ outp)
{
    extern __shared__ __align__(16) __half gsm[];

    const int t = threadIdx.x, lane = t & 31, wid = t >> 5;
    const int wm = wid >> 2, wn = wid & 3;           // 2 x 4
    const int m0 = blockIdx.y * 128;
    const int n0 = blockIdx.x * 128;

    const __half* __restrict__ Ahp = mode ? g_ah  : g_xh;
    const __half* __restrict__ Bhp = mode ? g_woh : g_wqh;
    const int Nw  = mode ? 1024 : 3072;
    const int NIT = 32;                              // K=1024, BK=32

    const int arow = t >> 1, acol = (t & 1) * 16;
    const int brow = t >> 3, bcol = (t & 7) * 16;
    const size_t aoff = (size_t)(m0 + arow) * 1024 + acol;
    const size_t boff = (size_t)brow * Nw + n0 + bcol;

    auto issue = [&](int it) {
        const int k0 = it * 32;
        __half* S  = gsm + (it % 3) * GS_STAGE;
        unsigned da = sptr(S + arow * 40 + acol);
        unsigned db = sptr(S + 128 * 40 + brow * 136 + bcol);
        const __half* ga = Ahp + aoff + k0;
        const __half* gb = Bhp + boff + (size_t)k0 * Nw;
        cp16(da,      ga);
        cp16(da + 16, ga + 8);
        cp16(db,      gb);
        cp16(db + 16, gb + 8);
        cp_commit();
    };

    float acc[4][4][4];
#pragma unroll
    for (int i = 0; i < 4; i++)
#pragma unroll
        for (int j = 0; j < 4; j++)
#pragma unroll
            for (int c = 0; c < 4; c++) acc[i][j][c] = 0.f;

    issue(0);
    issue(1);

    for (int it = 0; it < NIT; it++) {
        cp_wait1();
        __syncthreads();
        if (it + 2 < NIT) issue(it + 2);

        __half (*As)[40]  = (__half(*)[40]) (gsm + (it % 3) * GS_STAGE);
        __half (*Bs)[136] = (__half(*)[136])(gsm + (it % 3) * GS_STAGE + 128 * 40);

#pragma unroll
        for (int kk = 0; kk < 2; kk++) {
            const int kb = kk * 16;
            unsigned a[4][4];
#pragma unroll
            for (int mi = 0; mi < 4; mi++)
                ldsm_x4(a[mi][0], a[mi][1], a[mi][2], a[mi][3],
                        sptr(&As[wm * 64 + mi * 16 + (lane & 15)][kb + (lane >> 4) * 8]));
            unsigned bf[4][2];
#pragma unroll
            for (int hb = 0; hb < 2; hb++) {
                unsigned r0, r1, r2, r3;
                ldsm_x4t(r0, r1, r2, r3,
                         sptr(&Bs[kb + (lane & 15)][wn * 32 + hb * 16 + (lane >> 4) * 8]));
                bf[hb * 2][0] = r0;  bf[hb * 2][1] = r1;
                bf[hb * 2 + 1][0] = r2;  bf[hb * 2 + 1][1] = r3;
            }
#pragma unroll
            for (int mi = 0; mi < 4; mi++)
#pragma unroll
                for (int ni = 0; ni < 4; ni++)
                    mma16816(acc[mi][ni], a[mi][0], a[mi][1], a[mi][2], a[mi][3],
                             bf[ni][0], bf[ni][1]);
        }
    }

#pragma unroll
    for (int mi = 0; mi < 4; mi++) {
#pragma unroll
        for (int ni = 0; ni < 4; ni++) {
            const int gm = m0 + wm * 64 + mi * 16 + (lane >> 2);
            const int gn = n0 + wn * 32 + ni * 8 + (lane & 3) * 2;
            if (mode == 1) {
                *(float2*)&outp[(size_t)gm * 1024 + gn]       = make_float2(acc[mi][ni][0], acc[mi][ni][1]);
                *(float2*)&outp[(size_t)(gm + 8) * 1024 + gn] = make_float2(acc[mi][ni][2], acc[mi][ni][3]);
            } else {
                const int part = gn >> 10, lc = gn & 1023;
                __half* Hh = (part == 0) ? g_qh : (part == 1) ? g_kh : g_vh;
                *(__half2*)&Hh[(size_t)gm * 1024 + lc] =
                    __floats2half2_rn(acc[mi][ni][0], acc[mi][ni][1]);
                *(__half2*)&Hh[(size_t)(gm + 8) * 1024 + lc] =
                    __floats2half2_rn(acc[mi][ni][2], acc[mi][ni][3]);
            }
        }
    }
}

// ---------------------------------------------------------------------------
// Pass A: per (b, 128-l, 64-m) tile, loop h: S = Qh·Kh, P = exp(S/8) stored as
// mma C-FRAGMENTS (coalesced STG.128), z accumulated over heads; zinv stored
// as packed half2 fragments. Dynamic smem: Qh[128][72] + Kh[64][72] = 27648 B.
// ---------------------------------------------------------------------------
__global__ __launch_bounds__(256, 2) void zsum_kernel()
{
    extern __shared__ __half zsm[];
    __half (*Qh)[72] = (__half(*)[72])zsm;
    __half (*Kh)[72] = (__half(*)[72])(zsm + 128 * 72);

    const int t = threadIdx.x, lane = t & 31, wid = t >> 5;
    const int wm = wid >> 1, wn = wid & 1;          // 4 x 2, warp tile 32(l) x 32(m)
    const int mt = blockIdx.x;
    const int lt = blockIdx.y;
    const int m0 = mt * 64;
    const int l0 = lt * 128;
    const int b  = blockIdx.z;

    const int fbase0 = ((((wm * 2 + wn) * 2) * 2) * 32 + lane) * 8;

    float zacc[2][4][4];
#pragma unroll
    for (int i = 0; i < 2; i++)
#pragma unroll
        for (int j = 0; j < 4; j++)
#pragma unroll
            for (int c = 0; c < 4; c++) zacc[i][j][c] = 0.f;

    const int qr = t >> 1, qc = (t & 1) * 32;
    const int kr = t >> 2, kc = (t & 3) * 16;

    for (int h = 0; h < Hn; h++) {
        const size_t qbase = (size_t)b * LDf + (size_t)h * HSTRd + (size_t)l0 * Kd;
        const size_t kbase = (size_t)b * LDf + (size_t)h * HSTRd + (size_t)m0 * Kd;
        __syncthreads();
#pragma unroll
        for (int i = 0; i < 4; i++) {
            *(uint4*)&Qh[qr][qc + i * 8] = *(const uint4*)(g_qh + qbase + (size_t)qr * Kd + qc + i * 8);
        }
#pragma unroll
        for (int i = 0; i < 2; i++) {
            *(uint4*)&Kh[kr][kc + i * 8] = *(const uint4*)(g_kh + kbase + (size_t)kr * Kd + kc + i * 8);
        }
        __syncthreads();

        float sacc[2][4][4];
#pragma unroll
        for (int i = 0; i < 2; i++)
#pragma unroll
            for (int j = 0; j < 4; j++)
#pragma unroll
                for (int c = 0; c < 4; c++) sacc[i][j][c] = 0.f;

#pragma unroll
        for (int kk = 0; kk < 4; kk++) {
            const int kb = kk * 16;
            unsigned a[2][4];
#pragma unroll
            for (int mi = 0; mi < 2; mi++)
                ldsm_x4(a[mi][0], a[mi][1], a[mi][2], a[mi][3],
                        sptr(&Qh[wm * 32 + mi * 16 + (lane & 15)][kb + (lane >> 4) * 8]));
            unsigned bf[4][2];
#pragma unroll
            for (int hb = 0; hb < 2; hb++) {
                unsigned r0, r1, r2, r3;
                ldsm_x4(r0, r1, r2, r3,
                        sptr(&Kh[wn * 32 + hb * 16 + (lane & 15)][kb + (lane >> 4) * 8]));
                bf[hb * 2][0] = r0;  bf[hb * 2][1] = r2;
                bf[hb * 2 + 1][0] = r1;  bf[hb * 2 + 1][1] = r3;
            }
#pragma unroll
            for (int mi = 0; mi < 2; mi++)
#pragma unroll
                for (int ni = 0; ni < 4; ni++)
                    mma16816(sacc[mi][ni], a[mi][0], a[mi][1], a[mi][2], a[mi][3],
                             bf[ni][0], bf[ni][1]);
        }

        const size_t pb = (((size_t)(b * Hn + h) * 16 + lt) * 32 + mt) * PTILE;
#pragma unroll
        for (int mi = 0; mi < 2; mi++) {
            uint4 U0, U1;
            __half2* u0 = (__half2*)&U0;
            __half2* u1 = (__half2*)&U1;
#pragma unroll
            for (int ni = 0; ni < 4; ni++) {
                float p0 = __expf(sacc[mi][ni][0] * 0.125f);
                float p1 = __expf(sacc[mi][ni][1] * 0.125f);
                float p2 = __expf(sacc[mi][ni][2] * 0.125f);
                float p3 = __expf(sacc[mi][ni][3] * 0.125f);
                zacc[mi][ni][0] += p0; zacc[mi][ni][1] += p1;
                zacc[mi][ni][2] += p2; zacc[mi][ni][3] += p3;
                u0[ni] = __floats2half2_rn(p0, p1);
                u1[ni] = __floats2half2_rn(p2, p3);
            }
            const size_t o = pb + fbase0 + mi * 512;
            *(uint4*)(g_p + o)       = U0;
            *(uint4*)(g_p + o + 256) = U1;
        }
    }

    const size_t zb = (((size_t)b * 16 + lt) * 32 + mt) * PTILE;
#pragma unroll
    for (int mi = 0; mi < 2; mi++) {
        uint4 U0, U1;
        __half2* u0 = (__half2*)&U0;
        __half2* u1 = (__half2*)&U1;
#pragma unroll
        for (int ni = 0; ni < 4; ni++) {
            u0[ni] = __floats2half2_rn(__fdividef(1.f, zacc[mi][ni][0]),
                                       __fdividef(1.f, zacc[mi][ni][1]));
            u1[ni] = __floats2half2_rn(__fdividef(1.f, zacc[mi][ni][2]),
                                       __fdividef(1.f, zacc[mi][ni][3]));
        }
        const size_t o = zb + fbase0 + mi * 512;
        *(uint4*)(g_zif + o)       = U0;
        *(uint4*)(g_zif + o + 256) = U1;
    }
}

// ---------------------------------------------------------------------------
// Pass B: O[128 l, 64 kd] = sum_m (P * zinv) @ Vh per (b, h, l-tile).
// P and zinv loaded as fragments straight into mma A-operands.
// Static smem: Vhs[64][72] = 9216 B.
// ---------------------------------------------------------------------------
__global__ __launch_bounds__(256, 2) void apv_kernel()
{
    __shared__ __half Vhs[64][72];

    const int t = threadIdx.x, lane = t & 31, wid = t >> 5;
    const int wm = wid >> 1, wn = wid & 1;          // 4 x 2, warp tile 32(l) x 32(kd)
    const int lt = blockIdx.x;
    const int h  = blockIdx.y;
    const int b  = blockIdx.z;
    const int l0 = lt * 128;

    float acc[2][4][4];
#pragma unroll
    for (int i = 0; i < 2; i++)
#pragma unroll
        for (int j = 0; j < 4; j++)
#pragma unroll
            for (int c = 0; c < 4; c++) acc[i][j][c] = 0.f;

    const size_t vbase = (size_t)b * LDf + (size_t)h * HSTRd;
    const size_t pbase = ((size_t)(b * Hn + h) * 16 + lt) * 32 * PTILE;
    const size_t zbase = ((size_t)b * 16 + lt) * 32 * PTILE;

    const int vr = t >> 2, vc = (t & 3) * 16;

    for (int mt = 0; mt < 32; mt++) {
        const int m0 = mt * 64;
        __syncthreads();
#pragma unroll
        for (int i = 0; i < 2; i++) {
            *(uint4*)&Vhs[vr][vc + i * 8] = *(const uint4*)(g_vh + vbase + (size_t)(m0 + vr) * Kd + vc + i * 8);
        }
        __syncthreads();

        const size_t pb = pbase + (size_t)mt * PTILE;
        const size_t zb = zbase + (size_t)mt * PTILE;

#pragma unroll
        for (int j = 0; j < 2; j++) {
            uint4 M[2][2];
#pragma unroll
            for (int mi = 0; mi < 2; mi++)
#pragma unroll
                for (int rg = 0; rg < 2; rg++) {
                    const size_t o = (size_t)((((((wm * 2 + j) * 2 + mi) * 2 + rg) * 32) + lane) * 8);
                    uint4 P = *(const uint4*)(g_p + pb + o);
                    uint4 Z = *(const uint4*)(g_zif + zb + o);
                    const __half2* ph = (const __half2*)&P;
                    const __half2* zh = (const __half2*)&Z;
                    __half2* mh = (__half2*)&M[mi][rg];
                    mh[0] = __hmul2(ph[0], zh[0]);
                    mh[1] = __hmul2(ph[1], zh[1]);
                    mh[2] = __hmul2(ph[2], zh[2]);
                    mh[3] = __hmul2(ph[3], zh[3]);
                }

#pragma unroll
            for (int kq = 0; kq < 2; kq++) {
                const int kk = j * 2 + kq;
                const int kb = kk * 16;
                const int nb = kq * 2;
                unsigned bh[4][2];
#pragma unroll
                for (int hb = 0; hb < 2; hb++) {
                    unsigned r0, r1, r2, r3;
                    ldsm_x4t(r0, r1, r2, r3,
                             sptr(&Vhs[kb + (lane & 15)][wn * 32 + hb * 16 + (lane >> 4) * 8]));
                    bh[hb * 2][0] = r0; bh[hb * 2][1] = r1;
                    bh[hb * 2 + 1][0] = r2; bh[hb * 2 + 1][1] = r3;
                }
#pragma unroll
                for (int mi = 0; mi < 2; mi++) {
                    const unsigned* m0w = (const unsigned*)&M[mi][0];
                    const unsigned* m1w = (const unsigned*)&M[mi][1];
                    const unsigned a0 = m0w[nb], a2 = m0w[nb + 1];
                    const unsigned a1 = m1w[nb], a3 = m1w[nb + 1];
#pragma unroll
                    for (int ni = 0; ni < 4; ni++)
                        mma16816(acc[mi][ni], a0, a1, a2, a3, bh[ni][0], bh[ni][1]);
                }
            }
        }
    }

    // Epilogue: plain fp16 store of attended in concatted layout [b, l, h*64+kd]
#pragma unroll
    for (int mi = 0; mi < 2; mi++) {
#pragma unroll
        for (int ni = 0; ni < 4; ni++) {
            const int gl = l0 + wm * 32 + mi * 16 + (lane >> 2);
            const int gc = h * Kd + wn * 32 + ni * 8 + (lane & 3) * 2;
            *(__half2*)&g_ah[((size_t)b * Ln + gl) * 1024 + gc] =
                __floats2half2_rn(acc[mi][ni][0], acc[mi][ni][1]);
            *(__half2*)&g_ah[((size_t)b * Ln + gl + 8) * 1024 + gc] =
                __floats2half2_rn(acc[mi][ni][2], acc[mi][ni][3]);
        }
    }
}

// ---------------------------------------------------------------------------
// Launch
// ---------------------------------------------------------------------------
extern "C" void kernel_launch(void* const* d_in, const int* in_sizes, int n_in,
                              void* d_out, int out_size)
{
    const float* x    = (const float*)d_in[0];
    const float* wqkv = (const float*)d_in[1];
    const float* wo   = (const float*)d_in[2];
    float* out = (float*)d_out;

    cudaFuncSetAttribute(gemm_split, cudaFuncAttributeMaxDynamicSharedMemorySize, GS_STAGE * 3 * 2);
    cudaFuncSetAttribute(zsum_kernel, cudaFuncAttributeMaxDynamicSharedMemorySize, 27648);

    // 0) fp32 -> fp16 conversions
    split_kernel<<<4096, 256>>>(x,    0, Bn * LDf);
    split_kernel<<<2048, 256>>>(wqkv, 1, Dn * 3 * Dn);
    split_kernel<<<1024, 256>>>(wo,   2, Dn * Dn);

    // 1) QKV projection (1-pass fp16 GEMM) -> q/k/v fp16
    gemm_split<<<dim3(24, 64), 256, GS_STAGE * 3 * 2>>>(0, nullptr);

    // 2) Pass A: P fragments + zinv fragments
    zsum_kernel<<<dim3(32, 16, 4), 256, 27648>>>();

    // 3) Pass B: O = (P * zinv) @ Vh via direct fragment loads
    apv_kernel<<<dim3(16, 16, 4), 256>>>();

    // 4) Output projection (1-pass fp16 GEMM) -> d_out
    gemm_split<<<dim3(8, 64), 256, GS_STAGE * 3 * 2>>>(1, out);
}